// round 17
// baseline (speedup 1.0000x reference)
#include <cuda_runtime.h>
#include <cstdint>
#include <cstddef>

// segments (identical to R15/R16):
//  L1 fused striped: seg = (m<<9)|(c<<6)|(g<<1)|s -> [0,1024)
//  W2: 1024+o (128, len 512)  W3: 1152+o (64)  Wout: 1216+o (128)
#define NSEG     1344
#define SEG_W2   1024
#define SEG_W3   1152
#define SEG_WOUT 1216
#define LIST_MAX 655360
#define LIST_CAP 22016
#define ACTS     1.3333333730697632f
#define THREADS  1024
#define GRID     512

__device__ int d_scale_bits[5];
__device__ int d_cnt[NSEG];
__device__ int d_off[NSEG + 1];
__device__ __align__(16) unsigned short d_list[LIST_MAX];

__global__ void prep_scale(const float* __restrict__ W1a, const float* __restrict__ W1b,
                           const float* __restrict__ W2,  const float* __restrict__ W3,
                           const float* __restrict__ Wout)
{
    __shared__ float red[8];
    int m = blockIdx.x >> 5, part = blockIdx.x & 31;
    const float* W; int n;
    switch (m) {
        case 0: W = W1a;  n = 131072; break;
        case 1: W = W1b;  n = 131072; break;
        case 2: W = W2;   n = 65536;  break;
        case 3: W = W3;   n = 8192;   break;
        default: W = Wout; n = 8192;  break;
    }
    int chunk = n >> 5, lo = part * chunk;
    float mx = 0.0f;
    for (int i = lo + threadIdx.x; i < lo + chunk; i += 256)
        mx = fmaxf(mx, fabsf(W[i]));
    #pragma unroll
    for (int o = 16; o; o >>= 1) mx = fmaxf(mx, __shfl_xor_sync(~0u, mx, o));
    if ((threadIdx.x & 31) == 0) red[threadIdx.x >> 5] = mx;
    __syncthreads();
    if (threadIdx.x < 32) {
        float v = (threadIdx.x < 8) ? red[threadIdx.x] : 0.0f;
        #pragma unroll
        for (int o = 4; o; o >>= 1) v = fmaxf(v, __shfl_xor_sync(~0u, v, o));
        if (threadIdx.x == 0) atomicMax(&d_scale_bits[m], __float_as_int(v));
    }
}

struct LSeg { const float* rowp; int len; float s; };
__device__ __forceinline__ LSeg lseg_decode(int seg, const float* W2,
                                            const float* W3, const float* Wout)
{
    LSeg r;
    if (seg < SEG_W3) {
        r.rowp = W2 + (seg - SEG_W2) * 512; r.len = 512;
        r.s = __int_as_float(d_scale_bits[2]);
    } else if (seg < SEG_WOUT) {
        r.rowp = W3 + (seg - SEG_W3) * 128; r.len = 128;
        r.s = __int_as_float(d_scale_bits[3]);
    } else {
        r.rowp = Wout + (seg - SEG_WOUT) * 64; r.len = 64;
        r.s = __int_as_float(d_scale_bits[4]);
    }
    return r;
}

__global__ void prep_count(const float* __restrict__ W1a, const float* __restrict__ W1b,
                           const float* __restrict__ W2,  const float* __restrict__ W3,
                           const float* __restrict__ Wout)
{
    int lane = threadIdx.x & 31;
    int seg = blockIdx.x * 8 + (threadIdx.x >> 5);
    if (seg >= NSEG) return;
    if (seg < SEG_W2) {
        int m = seg >> 9, c = (seg >> 6) & 7, g = (seg >> 1) & 31, s = seg & 1;
        float sc = __int_as_float(d_scale_bits[m]);
        const float* base = (m ? W1b : W1a) + c * 128;
        int Lmax = 0;
        for (int j = 0; j < 4; j++) {
            const float* rowp = base + (size_t)((g << 2) + j) * 1024;
            int cnt = 0;
            for (int j0 = 0; j0 < 128; j0 += 32) {
                float qv = rintf(__fdiv_rn(rowp[j0 + lane], sc));
                bool nz = s ? (qv < 0.0f) : (qv > 0.0f);
                cnt += __popc(__ballot_sync(~0u, nz));
            }
            Lmax = max(Lmax, cnt);
        }
        if (lane == 0) d_cnt[seg] = 4 * ((Lmax + 1) & ~1);
    } else {
        LSeg si = lseg_decode(seg, W2, W3, Wout);
        int cnt = 0;
        for (int j0 = 0; j0 < si.len; j0 += 32) {
            float qv = rintf(__fdiv_rn(si.rowp[j0 + lane], si.s));
            cnt += __popc(__ballot_sync(~0u, qv != 0.0f));
        }
        if (lane == 0) d_cnt[seg] = (cnt + 3) & ~3;
    }
}

// entries: L1 fused: idx*66 (pad = 8448 -> zero column); layers: (idx<<2)|cls (1=+,2=-,0=pad)
__global__ void prep_scanfill(const float* __restrict__ W1a, const float* __restrict__ W1b,
                              const float* __restrict__ W2,  const float* __restrict__ W3,
                              const float* __restrict__ Wout)
{
    __shared__ int s_off[NSEG + 1];
    __shared__ int warpsum[8];
    int tid = threadIdx.x, lane = tid & 31, w = tid >> 5;
    {
        int base = tid * 6, v[6], s = 0;
        #pragma unroll
        for (int k = 0; k < 6; k++) {
            int idx = base + k;
            int c = (idx < NSEG) ? d_cnt[idx] : 0;
            v[k] = s; s += c;
        }
        int incl = s;
        #pragma unroll
        for (int o = 1; o < 32; o <<= 1) {
            int t = __shfl_up_sync(~0u, incl, o);
            if (lane >= o) incl += t;
        }
        if (lane == 31) warpsum[w] = incl;
        __syncthreads();
        if (w == 0 && lane < 8) {
            int ws = warpsum[lane];
            #pragma unroll
            for (int o = 1; o < 8; o <<= 1) {
                int t = __shfl_up_sync(0xffu, ws, o);
                if (lane >= o) ws += t;
            }
            warpsum[lane] = ws;
        }
        __syncthreads();
        int excl = incl - s + (w ? warpsum[w - 1] : 0);
        #pragma unroll
        for (int k = 0; k < 6; k++) {
            int idx = base + k;
            if (idx <= NSEG) s_off[idx] = excl + v[k];
        }
        __syncthreads();
    }
    if (blockIdx.x == 0)
        for (int i = tid; i <= NSEG; i += 256) d_off[i] = s_off[i];

    for (int seg = blockIdx.x * 8 + w; seg < NSEG; seg += gridDim.x * 8) {
        int base = s_off[seg];
        if (seg < SEG_W2) {
            int m = seg >> 9, c = (seg >> 6) & 7, g = (seg >> 1) & 31, s = seg & 1;
            float sc = __int_as_float(d_scale_bits[m]);
            int Lpad = (s_off[seg + 1] - base) >> 2;
            const float* wb = (m ? W1b : W1a) + c * 128;
            for (int j = 0; j < 4; j++) {
                const float* rowp = wb + (size_t)((g << 2) + j) * 1024;
                int i = 0;
                for (int j0 = 0; j0 < 128; j0 += 32) {
                    float qv = rintf(__fdiv_rn(rowp[j0 + lane], sc));
                    bool nz = s ? (qv < 0.0f) : (qv > 0.0f);
                    unsigned bal = __ballot_sync(~0u, nz);
                    if (nz) {
                        int pos = i + __popc(bal & ((1u << lane) - 1u));
                        d_list[base + pos * 4 + j] = (unsigned short)((j0 + lane) * 66);
                    }
                    i += __popc(bal);
                }
                for (int p = i + lane; p < Lpad; p += 32)
                    d_list[base + p * 4 + j] = (unsigned short)8448;
            }
        } else {
            LSeg si = lseg_decode(seg, W2, W3, Wout);
            int b = base;
            for (int j0 = 0; j0 < si.len; j0 += 32) {
                float qv = rintf(__fdiv_rn(si.rowp[j0 + lane], si.s));
                bool nz = (qv != 0.0f);
                unsigned bal = __ballot_sync(~0u, nz);
                if (nz) {
                    int pos = b + __popc(bal & ((1u << lane) - 1u));
                    d_list[pos] = (unsigned short)(((j0 + lane) << 2) | (qv > 0.0f ? 1 : 2));
                }
                b += __popc(bal);
            }
            int end = s_off[seg + 1];
            for (int p = b + lane; p < end; p += 32) d_list[p] = 0;
        }
    }
}

// smem layout identical to R16
#define XSBUF   34056
#define H1_OFF  136224
#define H2_OFF  170016
#define H3_OFF  178464
#define OFF_OFF 182688
#define MB_OFF  188072
#define LST_OFF 188144
#define SMEM_BYTES 232176

__device__ __forceinline__ float quant_relu_q(float y) {
    float qv = rintf(__fdiv_rn(y, ACTS));
    return fminf(fmaxf(qv, 0.0f), 3.0f);
}
__device__ __forceinline__ int csel(unsigned c, int v) {
    int r = (c == 1u) ? v : 0;
    return (c == 2u) ? -v : r;
}
__device__ __forceinline__ unsigned long long packf2(float lo, float hi) {
    unsigned long long r;
    asm("mov.b64 %0, {%1, %2};" : "=l"(r) : "f"(lo), "f"(hi));
    return r;
}
__device__ __forceinline__ void unpackf2(float& lo, float& hi, unsigned long long v) {
    asm("mov.b64 {%0, %1}, %2;" : "=f"(lo), "=f"(hi) : "l"(v));
}
__device__ __forceinline__ void fma2(unsigned long long& a, unsigned long long w,
                                     unsigned long long v) {
    asm("fma.rn.f32x2 %0, %1, %2, %3;" : "=l"(a) : "l"(w), "l"(v), "l"(a));
}

#define MB_INIT(a, c) asm volatile("mbarrier.init.shared.b64 [%0], %1;" :: "r"(a), "r"(c) : "memory")
#define MB_ARRIVE(a)  asm volatile("mbarrier.arrive.shared.b64 _, [%0];" :: "r"(a) : "memory")
#define MB_WAIT(a, ph) do { \
    unsigned _m = (a), _p = (ph), _d; \
    asm volatile("{\n\t.reg .pred p;\n\t" \
        "mbarrier.try_wait.parity.acquire.cta.shared::cta.b64 p, [%1], %2;\n\t" \
        "selp.b32 %0, 1, 0, p;\n\t}" : "=r"(_d) : "r"(_m), "r"(_p) : "memory"); \
    if (!_d) { \
        asm volatile("{\n\t.reg .pred P1;\n\t" \
            "WL_%=:\n\t" \
            "mbarrier.try_wait.parity.acquire.cta.shared::cta.b64 P1, [%0], %1, 0x989680;\n\t" \
            "@P1 bra.uni WD_%=;\n\t" \
            "bra.uni WL_%=;\n\t" \
            "WD_%=:\n\t}" :: "r"(_m), "r"(_p) : "memory"); \
    } } while (0)

#define LDSV2(r0_, r1_, a_) \
    asm("ld.shared.v2.u32 {%0,%1}, [%2];" : "=r"(r0_), "=r"(r1_) : "r"(a_))

#define CP4(dst, src) \
    asm volatile("cp.async.ca.shared.global [%0], [%1], 4;" :: "r"(dst), "l"(src))
#define CP_COMMIT() asm volatile("cp.async.commit_group;" ::: "memory")
#define CP_WAIT0()  asm volatile("cp.async.wait_group 0;" ::: "memory")

// dual-strip entry: strip A at [curb + ev*4], strip C in adjacent buffer (+XSBUF)
#define FE2(aA, aC, ev) { \
    unsigned long long vA_, vC_; \
    unsigned ad_ = curb + ((ev) << 2); \
    asm("ld.shared.b64 %0, [%1];" : "=l"(vA_) : "r"(ad_)); \
    asm("ld.shared.b64 %0, [%1+34056];" : "=l"(vC_) : "r"(ad_)); \
    fma2(aA, wpx, vA_); fma2(aC, wpx, vC_); }

template<bool USE_SM>
__device__ __forceinline__ void ld_pack4(unsigned& w0, unsigned& w1, unsigned lstsh, int p)
{
    if (USE_SM) {
        LDSV2(w0, w1, lstsh + (p << 1));
    } else {
        uint2 A = *(const uint2*)(d_list + p);
        w0 = A.x; w1 = A.y;
    }
}

// stage tile s = (m<<4)|(chunk<<1)|strip via cp.async (8 x 4B per thread)
__device__ __forceinline__ void stage_cp(unsigned smem_sh, const float* x, int row0,
                                         int srow, int cl, int s)
{
    int ms = s >> 4, cs = (s >> 1) & 7, strip = s & 1;
    const float* src = x + (size_t)(row0 + srow) * 4096
                     + strip * 2048 + ms * 1024 + cs * 128 + cl;
    unsigned dst = smem_sh + (unsigned)((s & 3) * XSBUF)
                 + (unsigned)((cl * 66 + srow) << 2);
    #pragma unroll
    for (int k = 0; k < 8; k++)
        CP4(dst + k * 4224, src + (k << 4));
    CP_COMMIT();
}

template<bool USE_SM>
__device__ __forceinline__ void mlp_body(
    unsigned char* smem, unsigned smem_sh,
    const float* __restrict__ x,
    const float* __restrict__ b1a, const float* __restrict__ b1b,
    const float* __restrict__ b2,  const float* __restrict__ b3,
    float* __restrict__ out, int row0)
{
    unsigned char* h1s = smem + H1_OFF;
    unsigned char* h2s = smem + H2_OFF;
    unsigned char* h3s = smem + H3_OFF;
    int* s_off = (int*)(smem + OFF_OFF);
    const unsigned lstsh = smem_sh + LST_OFF;
    float* outs = (float*)(smem);

    const int tid = threadIdx.x, lane = tid & 31, g = tid >> 5;
    const int r2 = lane << 1;
    const int srow = (g << 1) + (lane >> 4);
    const int cl = lane & 15;

    const float sc1a = __int_as_float(d_scale_bits[0]);
    const float sc1b = __int_as_float(d_scale_bits[1]);
    const float s2 = __int_as_float(d_scale_bits[2]);
    const float s3 = __int_as_float(d_scale_bits[3]);
    const float s4 = __int_as_float(d_scale_bits[4]);

    const unsigned mb = smem_sh + MB_OFF;   // FULL[b]=mb+8b, FREE[b]=mb+32+8b

    // prologue: stage tiles 0,1 (buffers 0,1)
    stage_cp(smem_sh, x, row0, srow, cl, 0);
    stage_cp(smem_sh, x, row0, srow, cl, 1);
    CP_WAIT0();
    __syncwarp();
    if (lane == 0) { MB_ARRIVE(mb + 0); MB_ARRIVE(mb + 8); }

    unsigned long long aA[4], aC[4];
    #pragma unroll
    for (int j = 0; j < 4; j++) { aA[j] = 0ull; aC[j] = 0ull; }

    #pragma unroll 1
    for (int k = 0; k < 16; ++k) {
        const int m = k >> 3, chunk = k & 7;
        const int bA = (2 * k) & 3;               // 0 or 2; strip C = bA+1
        const int s1 = 2 * k + 2, s2i = 2 * k + 3;

        // issue staging for next pair (overlaps this step's compute)
        if (s1 < 32) {
            if (s1 >= 4) MB_WAIT(mb + 32 + ((s1 & 3) << 3), ((s1 >> 2) - 1) & 1);
            if (s2i >= 4) MB_WAIT(mb + 32 + ((s2i & 3) << 3), ((s2i >> 2) - 1) & 1);
            stage_cp(smem_sh, x, row0, srow, cl, s1);
            stage_cp(smem_sh, x, row0, srow, cl, s2i);
        }

        MB_WAIT(mb + (bA << 3), (k >> 1) & 1);
        MB_WAIT(mb + ((bA + 1) << 3), (k >> 1) & 1);

        const unsigned curb = smem_sh + bA * XSBUF + (unsigned)(r2 << 2);
        const float sc = m ? sc1b : sc1a;
        const unsigned long long wpos = packf2(sc, sc);
        const unsigned long long wneg = packf2(-sc, -sc);
        {
            int sb = (m << 9) + (chunk << 6) + (g << 1);
            int p0 = s_off[sb], p1 = s_off[sb + 1], p2 = s_off[sb + 2];
            unsigned long long tA0 = aA[0], tA1 = aA[1], tA2 = aA[2], tA3 = aA[3];
            unsigned long long tC0 = aC[0], tC1 = aC[1], tC2 = aC[2], tC3 = aC[3];
            unsigned long long wpx = wpos;
            for (int p = p0; p < p1; p += 8) {
                unsigned u0, u1, u2, u3;
                ld_pack4<USE_SM>(u0, u1, lstsh, p);
                ld_pack4<USE_SM>(u2, u3, lstsh, p + 4);
                FE2(tA0, tC0, u0 & 0xffffu); FE2(tA1, tC1, u0 >> 16);
                FE2(tA2, tC2, u1 & 0xffffu); FE2(tA3, tC3, u1 >> 16);
                FE2(tA0, tC0, u2 & 0xffffu); FE2(tA1, tC1, u2 >> 16);
                FE2(tA2, tC2, u3 & 0xffffu); FE2(tA3, tC3, u3 >> 16);
            }
            wpx = wneg;
            for (int p = p1; p < p2; p += 8) {
                unsigned u0, u1, u2, u3;
                ld_pack4<USE_SM>(u0, u1, lstsh, p);
                ld_pack4<USE_SM>(u2, u3, lstsh, p + 4);
                FE2(tA0, tC0, u0 & 0xffffu); FE2(tA1, tC1, u0 >> 16);
                FE2(tA2, tC2, u1 & 0xffffu); FE2(tA3, tC3, u1 >> 16);
                FE2(tA0, tC0, u2 & 0xffffu); FE2(tA1, tC1, u2 >> 16);
                FE2(tA2, tC2, u3 & 0xffffu); FE2(tA3, tC3, u3 >> 16);
            }
            aA[0] = tA0; aA[1] = tA1; aA[2] = tA2; aA[3] = tA3;
            aC[0] = tC0; aC[1] = tC1; aC[2] = tC2; aC[3] = tC3;
        }

        if (chunk == 7) {     // branches m (strip A) and m+2 (strip C) complete
            const float* bb = m ? b1b : b1a;
            #pragma unroll
            for (int j = 0; j < 4; j++) {
                int o = (g << 2) + j;
                float bv = bb[o];
                float x0, x1;
                unpackf2(x0, x1, aA[j]);
                unsigned cA0 = (unsigned)(int)quant_relu_q(x0 + bv);
                unsigned cA1 = (unsigned)(int)quant_relu_q(x1 + bv);
                *(unsigned short*)(h1s + (m * 128 + o) * 66 + r2) =
                    (unsigned short)(cA0 | (cA1 << 8));
                unpackf2(x0, x1, aC[j]);
                unsigned cC0 = (unsigned)(int)quant_relu_q(x0 + bv);
                unsigned cC1 = (unsigned)(int)quant_relu_q(x1 + bv);
                *(unsigned short*)(h1s + ((m + 2) * 128 + o) * 66 + r2) =
                    (unsigned short)(cC0 | (cC1 << 8));
                aA[j] = 0ull; aC[j] = 0ull;
            }
        }
        __syncwarp();
        if (lane == 0) {
            MB_ARRIVE(mb + 32 + (bA << 3));
            MB_ARRIVE(mb + 32 + ((bA + 1) << 3));
        }

        if (s1 < 32) {
            CP_WAIT0();
            __syncwarp();
            if (lane == 0) {
                MB_ARRIVE(mb + ((s1 & 3) << 3));
                MB_ARRIVE(mb + ((s2i & 3) << 3));
            }
        }
    }
    __syncthreads();

    // ---- layer 2 ----
    #pragma unroll
    for (int j = 0; j < 4; j++) {
        int o = (g << 2) + j;
        int seg = SEG_W2 + o;
        int p0 = s_off[seg], p1 = s_off[seg + 1];
        int is0 = 0, is1 = 0;
        for (int p = p0; p < p1; p += 4) {
            unsigned w0, w1;
            ld_pack4<USE_SM>(w0, w1, lstsh, p);
            unsigned e0 = w0 & 0xffffu, e1 = w0 >> 16;
            unsigned e2 = w1 & 0xffffu, e3 = w1 >> 16;
            unsigned c0 = *(const unsigned short*)(h1s + (e0 >> 2) * 66 + r2);
            unsigned c1 = *(const unsigned short*)(h1s + (e1 >> 2) * 66 + r2);
            unsigned c2 = *(const unsigned short*)(h1s + (e2 >> 2) * 66 + r2);
            unsigned c3 = *(const unsigned short*)(h1s + (e3 >> 2) * 66 + r2);
            is0 += csel(e0 & 3u, (int)(c0 & 0xffu)) + csel(e1 & 3u, (int)(c1 & 0xffu))
                 + csel(e2 & 3u, (int)(c2 & 0xffu)) + csel(e3 & 3u, (int)(c3 & 0xffu));
            is1 += csel(e0 & 3u, (int)(c0 >> 8)) + csel(e1 & 3u, (int)(c1 >> 8))
                 + csel(e2 & 3u, (int)(c2 >> 8)) + csel(e3 & 3u, (int)(c3 >> 8));
        }
        float bv = b2[o];
        unsigned q0 = (unsigned)(int)quant_relu_q(fmaf((float)is0 * ACTS, s2, bv));
        unsigned q1 = (unsigned)(int)quant_relu_q(fmaf((float)is1 * ACTS, s2, bv));
        *(unsigned short*)(h2s + o * 66 + r2) = (unsigned short)(q0 | (q1 << 8));
    }
    __syncthreads();

    // ---- layer 3 ----
    #pragma unroll
    for (int j = 0; j < 2; j++) {
        int o = (g << 1) + j;
        int seg = SEG_W3 + o;
        int p0 = s_off[seg], p1 = s_off[seg + 1];
        int is0 = 0, is1 = 0;
        for (int p = p0; p < p1; p += 4) {
            unsigned w0, w1;
            ld_pack4<USE_SM>(w0, w1, lstsh, p);
            unsigned e0 = w0 & 0xffffu, e1 = w0 >> 16;
            unsigned e2 = w1 & 0xffffu, e3 = w1 >> 16;
            unsigned c0 = *(const unsigned short*)(h2s + (e0 >> 2) * 66 + r2);
            unsigned c1 = *(const unsigned short*)(h2s + (e1 >> 2) * 66 + r2);
            unsigned c2 = *(const unsigned short*)(h2s + (e2 >> 2) * 66 + r2);
            unsigned c3 = *(const unsigned short*)(h2s + (e3 >> 2) * 66 + r2);
            is0 += csel(e0 & 3u, (int)(c0 & 0xffu)) + csel(e1 & 3u, (int)(c1 & 0xffu))
                 + csel(e2 & 3u, (int)(c2 & 0xffu)) + csel(e3 & 3u, (int)(c3 & 0xffu));
            is1 += csel(e0 & 3u, (int)(c0 >> 8)) + csel(e1 & 3u, (int)(c1 >> 8))
                 + csel(e2 & 3u, (int)(c2 >> 8)) + csel(e3 & 3u, (int)(c3 >> 8));
        }
        float bv = b3[o];
        unsigned q0 = (unsigned)(int)quant_relu_q(fmaf((float)is0 * ACTS, s3, bv));
        unsigned q1 = (unsigned)(int)quant_relu_q(fmaf((float)is1 * ACTS, s3, bv));
        *(unsigned short*)(h3s + o * 66 + r2) = (unsigned short)(q0 | (q1 << 8));
    }
    __syncthreads();

    // ---- output layer ----
    #pragma unroll
    for (int j = 0; j < 4; j++) {
        int o = (g << 2) + j;
        int seg = SEG_WOUT + o;
        int p0 = s_off[seg], p1 = s_off[seg + 1];
        int is0 = 0, is1 = 0;
        for (int p = p0; p < p1; p += 4) {
            unsigned w0, w1;
            ld_pack4<USE_SM>(w0, w1, lstsh, p);
            unsigned e0 = w0 & 0xffffu, e1 = w0 >> 16;
            unsigned e2 = w1 & 0xffffu, e3 = w1 >> 16;
            unsigned c0 = *(const unsigned short*)(h3s + (e0 >> 2) * 66 + r2);
            unsigned c1 = *(const unsigned short*)(h3s + (e1 >> 2) * 66 + r2);
            unsigned c2 = *(const unsigned short*)(h3s + (e2 >> 2) * 66 + r2);
            unsigned c3 = *(const unsigned short*)(h3s + (e3 >> 2) * 66 + r2);
            is0 += csel(e0 & 3u, (int)(c0 & 0xffu)) + csel(e1 & 3u, (int)(c1 & 0xffu))
                 + csel(e2 & 3u, (int)(c2 & 0xffu)) + csel(e3 & 3u, (int)(c3 & 0xffu));
            is1 += csel(e0 & 3u, (int)(c0 >> 8)) + csel(e1 & 3u, (int)(c1 >> 8))
                 + csel(e2 & 3u, (int)(c2 >> 8)) + csel(e3 & 3u, (int)(c3 >> 8));
        }
        outs[(r2 + 0) * 132 + o] = ((float)is0 * ACTS) * s4;
        outs[(r2 + 1) * 132 + o] = ((float)is1 * ACTS) * s4;
    }
    __syncthreads();

    #pragma unroll
    for (int k = 0; k < 2; k++) {
        int qi = tid + (k << 10);
        int rr = qi >> 5, c4 = qi & 31;
        float4 v = *(const float4*)&outs[rr * 132 + (c4 << 2)];
        *(float4*)&out[(size_t)(row0 + rr) * 128 + (c4 << 2)] = v;
    }
}

__global__ void __launch_bounds__(THREADS, 1) mlp_main(
    const float* __restrict__ x,
    const float* __restrict__ b1a, const float* __restrict__ b1b,
    const float* __restrict__ b2,  const float* __restrict__ b3,
    float* __restrict__ out)
{
    extern __shared__ unsigned char smem[];
    int* s_off = (int*)(smem + OFF_OFF);
    unsigned int* s_list = (unsigned int*)(smem + LST_OFF);
    unsigned smem_sh = (unsigned)__cvta_generic_to_shared(smem);

    const int tid = threadIdx.x;
    const int row0 = blockIdx.x << 6;

    if (tid < 8) MB_INIT(smem_sh + MB_OFF + (tid << 3), 32);
    // zero column (words 8448..8513) in all 4 buffers
    if (tid >= 32 && tid < 296) {
        int q = tid - 32;
        ((float*)smem)[(q >> 6) * (XSBUF / 4) + 8448 + (q & 63)] = 0.0f;
    }
    if (tid >= 296 && tid < 304)
        ((float*)smem)[((tid - 296) >> 1) * (XSBUF / 4) + 8512 + ((tid - 296) & 1)] = 0.0f;

    for (int i = tid; i <= NSEG; i += THREADS) s_off[i] = d_off[i];
    const int total = d_off[NSEG];
    const bool use_sm = (total <= LIST_CAP);
    if (use_sm) {
        const unsigned int* src = (const unsigned int*)d_list;
        int n32 = (total + 1) >> 1;
        for (int i = tid; i < n32; i += THREADS) s_list[i] = src[i];
    }
    __syncthreads();

    if (use_sm) mlp_body<true>(smem, smem_sh, x, b1a, b1b, b2, b3, out, row0);
    else        mlp_body<false>(smem, smem_sh, x, b1a, b1b, b2, b3, out, row0);
}

extern "C" void kernel_launch(void* const* d_in, const int* in_sizes, int n_in,
                              void* d_out, int out_size)
{
    const float* x    = (const float*)d_in[0];
    const float* W1a  = (const float*)d_in[1];
    const float* b1a  = (const float*)d_in[2];
    const float* W1b  = (const float*)d_in[3];
    const float* b1b  = (const float*)d_in[4];
    const float* W2   = (const float*)d_in[5];
    const float* b2   = (const float*)d_in[6];
    const float* W3   = (const float*)d_in[7];
    const float* b3   = (const float*)d_in[8];
    const float* Wout = (const float*)d_in[9];
    float* out = (float*)d_out;

    prep_scale<<<160, 256>>>(W1a, W1b, W2, W3, Wout);
    prep_count<<<NSEG / 8, 256>>>(W1a, W1b, W2, W3, Wout);
    prep_scanfill<<<148, 256>>>(W1a, W1b, W2, W3, Wout);

    cudaFuncSetAttribute(mlp_main, cudaFuncAttributeMaxDynamicSharedMemorySize, SMEM_BYTES);
    mlp_main<<<GRID, THREADS, SMEM_BYTES>>>(x, b1a, b1b, b2, b3, out);
}